// round 16
// baseline (speedup 1.0000x reference)
#include <cuda_runtime.h>
#include <cuda_fp16.h>
#include <math.h>
#include <stdint.h>

// Problem constants
#define BB 8
#define SS 8192
#define DD 64
#define HH 8
#define NCHUNK 1024
#define SELF_VAL -5e4f

// ---------------- warp MMA helpers (sm_80-class, compute_103-safe) -----------
__device__ __forceinline__ uint32_t smem_u32(const void* p) {
    uint32_t a;
    asm("{ .reg .u64 t; cvta.to.shared.u64 t, %1; cvt.u32.u64 %0, t; }"
        : "=r"(a) : "l"(p));
    return a;
}
__device__ __forceinline__ void ldm_x4(uint32_t* r, uint32_t addr) {
    asm volatile("ldmatrix.sync.aligned.m8n8.x4.shared.b16 {%0,%1,%2,%3}, [%4];"
                 : "=r"(r[0]), "=r"(r[1]), "=r"(r[2]), "=r"(r[3]) : "r"(addr));
}
__device__ __forceinline__ void ldm_x4t(uint32_t* r, uint32_t addr) {
    asm volatile("ldmatrix.sync.aligned.m8n8.x4.trans.shared.b16 {%0,%1,%2,%3}, [%4];"
                 : "=r"(r[0]), "=r"(r[1]), "=r"(r[2]), "=r"(r[3]) : "r"(addr));
}
__device__ __forceinline__ void mma16816(float* c, const uint32_t* a,
                                         uint32_t b0, uint32_t b1) {
    asm volatile(
        "mma.sync.aligned.m16n8k16.row.col.f32.f16.f16.f32 "
        "{%0,%1,%2,%3}, {%4,%5,%6,%7}, {%8,%9}, {%0,%1,%2,%3};"
        : "+f"(c[0]), "+f"(c[1]), "+f"(c[2]), "+f"(c[3])
        : "r"(a[0]), "r"(a[1]), "r"(a[2]), "r"(a[3]), "r"(b0), "r"(b1));
}
__device__ __forceinline__ uint32_t h2pack(float x, float y) {
    __half2 h = __floats2half2_rn(x, y);
    return *(uint32_t*)&h;
}
__device__ __forceinline__ uint32_t hpackh(__half x, __half y) {
    __half2 h = __halves2half2(x, y);
    return *(uint32_t*)&h;
}

// key-column (0..127) -> tile row (0..191)
__device__ __forceinline__ int kmap(int p, int col) {
    if (p == 0) return (col < 64) ? col : col + 64;
    return (col < 64) ? col + 64 : col - 64;
}

// ---------------- scratch ----------------------------------------------------
__device__ int      g_bucket[BB * HH * SS];
__device__ int      g_st[BB * HH * SS];
__device__ float    g_logits[BB * HH * SS];
__device__ uint32_t g_oh[(size_t)BB * HH * SS * 32];   // fp16x2 outputs, 64 MB
__device__ uint32_t g_kh[(size_t)BB * SS * 32];        // fp16 qk hi-split, 8 MB
__device__ uint32_t g_klo[(size_t)BB * SS * 32];       // fp16 qk lo-split, 8 MB
__device__ uint32_t g_vh[(size_t)BB * SS * 32];        // fp16 v,  8 MB
__device__ uint32_t g_rhi[HH * 64 * 32];               // fp16 rot hi, 64 KB
__device__ uint32_t g_rlo[HH * 64 * 32];               // fp16 rot lo, 64 KB
__device__ float    g_invn[BB * SS];                   // exact fp32 inv-norms
__device__ int      g_nflag;                           // near-tie counter
__device__ int      g_flag[BB * HH * SS];              // flagged token-rounds

// ---------------- kernel 0a: rotation pre-split (once, not per hash block) ---
// rot layout [f][h][i]; write g_rhi/g_rlo as [h][f][i] fp16 (128 B per f-row).
__global__ void rsplit_kernel(const float* __restrict__ rot)
{
    int idx = blockIdx.x * 256 + threadIdx.x;   // 0..8191 float4s
    int f   = idx >> 7;
    int rem = idx & 127;
    int h   = rem >> 4, i4 = rem & 15;

    float4 x = ((const float4*)rot)[idx];
    __half a0 = __float2half_rn(x.x), a1 = __float2half_rn(x.y);
    __half a2 = __float2half_rn(x.z), a3 = __float2half_rn(x.w);
    uint2 hiv; hiv.x = hpackh(a0, a1); hiv.y = hpackh(a2, a3);
    uint2 lov;
    lov.x = h2pack(x.x - __half2float(a0), x.y - __half2float(a1));
    lov.y = h2pack(x.z - __half2float(a2), x.w - __half2float(a3));
    int dst = (h * 64 + f) * 16 + i4;
    ((uint2*)g_rhi)[dst] = hiv;
    ((uint2*)g_rlo)[dst] = lov;
}

// ---------------- kernel 0b: fp16 pre-pass (hi+lo split) + exact norms -------
__global__ void prep_kernel(const float* __restrict__ qk,
                            const float* __restrict__ v)
{
    if (blockIdx.x == 0 && threadIdx.x == 0) g_nflag = 0;

    int idx = blockIdx.x * 256 + threadIdx.x;   // token*16 + f4
    int f4  = idx & 15;
    int tok = idx >> 4;

    float4 kx = ((const float4*)qk)[idx];
    float4 vx = ((const float4*)v)[idx];

    __half a0 = __float2half_rn(kx.x), a1 = __float2half_rn(kx.y);
    __half a2 = __float2half_rn(kx.z), a3 = __float2half_rn(kx.w);
    uint2 kk; kk.x = hpackh(a0, a1); kk.y = hpackh(a2, a3);
    ((uint2*)g_kh)[tok * 16 + f4] = kk;
    uint2 kl;
    kl.x = h2pack(kx.x - __half2float(a0), kx.y - __half2float(a1));
    kl.y = h2pack(kx.z - __half2float(a2), kx.w - __half2float(a3));
    ((uint2*)g_klo)[tok * 16 + f4] = kl;

    uint2 vv; vv.x = h2pack(vx.x, vx.y); vv.y = h2pack(vx.z, vx.w);
    ((uint2*)g_vh)[tok * 16 + f4] = vv;

    float sq = kx.x * kx.x + kx.y * kx.y + kx.z * kx.z + kx.w * kx.w;
    sq += __shfl_xor_sync(0xffffffffu, sq, 1);
    sq += __shfl_xor_sync(0xffffffffu, sq, 2);
    sq += __shfl_xor_sync(0xffffffffu, sq, 4);
    sq += __shfl_xor_sync(0xffffffffu, sq, 8);
    if (f4 == 0) g_invn[tok] = 1.0f / (sqrtf(sq) + 1e-6f);
}

// ---------------- kernel 1: LSH hash stage A — fp16-split HMMA filter ---------
#define HQHI 0
#define HQLO 16384
#define HRHI 32768
#define HRLO 40960

#define TOP2(v, c, v1, i1, v2) do {                                   \
    float _av = fabsf(v);                                             \
    int _ci = ((v) >= 0.f) ? (c) : (64 + (c));                        \
    if (_av > (v1) || (_av == (v1) && _ci < (i1))) {                  \
        (v2) = (v1); (v1) = _av; (i1) = _ci;                          \
    } else (v2) = fmaxf((v2), _av); } while (0)

#define MERGE2(v1, i1, v2, m) do {                                    \
    float _ov1 = __shfl_xor_sync(0xffffffffu, (v1), (m));             \
    int   _oi1 = __shfl_xor_sync(0xffffffffu, (i1), (m));             \
    float _ov2 = __shfl_xor_sync(0xffffffffu, (v2), (m));             \
    if (_ov1 > (v1) || (_ov1 == (v1) && _oi1 < (i1))) {               \
        (v2) = fmaxf((v1), _ov2); (v1) = _ov1; (i1) = _oi1;           \
    } else (v2) = fmaxf((v2), _ov1); } while (0)

__global__ void __launch_bounds__(256)
hash_kernel(const float* __restrict__ qk, const float* __restrict__ rot)
{
    __shared__ char sm[49152];
    uint32_t sbase = smem_u32(sm);

    int blk  = blockIdx.x;
    int tile = blk & 63;
    int h    = (blk >> 6) & 7;
    int b    = blk >> 9;
    int tid  = threadIdx.x;
    int w = tid >> 5, l = tid & 31;

    // ---- Q load: pre-split fp16 hi/lo straight from global (coalesced) -------
    const uint4* kh4 = (const uint4*)g_kh + ((size_t)b * SS + tile * 128) * 8;
    const uint4* kl4 = (const uint4*)g_klo + ((size_t)b * SS + tile * 128) * 8;
#pragma unroll
    for (int it = 0; it < 4; it++) {
        int idx = tid + it * 256;        // 0..1023 = row*8 + f8
        int row = idx >> 3, f8 = idx & 7;
        uint32_t off = (uint32_t)(row * 128 + f8 * 16) ^ ((uint32_t)(row & 7) << 4);
        *(uint4*)(sm + HQHI + off) = kh4[idx];
        *(uint4*)(sm + HQLO + off) = kl4[idx];
    }

    // ---- R load: pre-split fp16 hi/lo straight from global (coalesced) -------
    const uint4* rh4 = (const uint4*)g_rhi + h * 512;   // 64 rows x 8 uint4
    const uint4* rl4 = (const uint4*)g_rlo + h * 512;
#pragma unroll
    for (int it = 0; it < 2; it++) {
        int idx = tid + it * 256;        // 0..511 = f*8 + f8
        int f = idx >> 3, f8 = idx & 7;
        uint32_t off = (uint32_t)(f * 128 + f8 * 16) ^ ((uint32_t)(f & 7) << 4);
        *(uint4*)(sm + HRHI + off) = rh4[idx];
        *(uint4*)(sm + HRLO + off) = rl4[idx];
    }
    __syncthreads();

    // ---- MMA: warp w handles rows w*16..+15, all 64 rotation cols -------------
    int qb = w * 16;
    int g  = l >> 2, i4 = l & 3;
    int m8 = l >> 3, rin = l & 7;

    float acc[8][4];
#pragma unroll
    for (int nt = 0; nt < 8; nt++)
#pragma unroll
        for (int k = 0; k < 4; k++) acc[nt][k] = 0.f;

#pragma unroll
    for (int kk = 0; kk < 4; kk++) {
        int arow = qb + ((m8 & 1) << 3) + rin;
        uint32_t adb = (uint32_t)((kk * 16 + ((m8 >> 1) << 3)) * 2);
        uint32_t aoff = (uint32_t)(arow * 128) + (adb ^ ((uint32_t)(arow & 7) << 4));
        uint32_t ahi[4], alo[4];
        ldm_x4(ahi, sbase + HQHI + aoff);
        ldm_x4(alo, sbase + HQLO + aoff);

        int brow = kk * 16 + ((m8 & 1) << 3) + rin;
#pragma unroll
        for (int n16 = 0; n16 < 4; n16++) {
            uint32_t bcol = (uint32_t)((n16 * 16 + ((m8 >> 1) << 3)) * 2);
            uint32_t boff = (uint32_t)(brow * 128) + (bcol ^ ((uint32_t)(brow & 7) << 4));
            uint32_t bhi[4], blo[4];
            ldm_x4t(bhi, sbase + HRHI + boff);
            ldm_x4t(blo, sbase + HRLO + boff);
            mma16816(acc[2 * n16],     ahi, bhi[0], bhi[1]);
            mma16816(acc[2 * n16 + 1], ahi, bhi[2], bhi[3]);
            mma16816(acc[2 * n16],     alo, bhi[0], bhi[1]);
            mma16816(acc[2 * n16 + 1], alo, bhi[2], bhi[3]);
            mma16816(acc[2 * n16],     ahi, blo[0], blo[1]);
            mma16816(acc[2 * n16 + 1], ahi, blo[2], blo[3]);
        }
    }

    // ---- top-2 over the 128 concat candidates, per row ------------------------
    float v1a = -1e30f, v2a = -1e30f, v1b = -1e30f, v2b = -1e30f;
    int i1a = 0, i1b = 0;
#pragma unroll
    for (int nt = 0; nt < 8; nt++) {
        int c = nt * 8 + 2 * i4;
        TOP2(acc[nt][0], c,     v1a, i1a, v2a);
        TOP2(acc[nt][1], c + 1, v1a, i1a, v2a);
        TOP2(acc[nt][2], c,     v1b, i1b, v2b);
        TOP2(acc[nt][3], c + 1, v1b, i1b, v2b);
    }
    MERGE2(v1a, i1a, v2a, 1); MERGE2(v1a, i1a, v2a, 2);
    MERGE2(v1b, i1b, v2b, 1); MERGE2(v1b, i1b, v2b, 2);

    if (i4 == 0) {
        int base = (b * HH + h) * SS + tile * 128;
#pragma unroll
        for (int rr = 0; rr < 2; rr++) {
            int row = qb + g + rr * 8;
            float v1 = rr ? v1b : v1a, v2 = rr ? v2b : v2a;
            int i1 = rr ? i1b : i1a;
            int t = tile * 128 + row;
            float nq = 1.0f / g_invn[b * SS + t];
            float theta = 5e-5f + 2e-5f * nq;
            if (v1 - v2 > theta) {
                g_bucket[base + row] = i1;
            } else {
                int s = atomicAdd(&g_nflag, 1);
                g_flag[s] = base + row;
            }
        }
    }
}

// ---------------- kernel 1b: exact fp32 fallback for near-tie tokens ----------
__global__ void hash_fix_kernel(const float* __restrict__ qk,
                                const float* __restrict__ rot)
{
    int n = g_nflag;
    for (int e = blockIdx.x * 128 + threadIdx.x; e < n; e += gridDim.x * 128) {
        int idx = g_flag[e];
        int t  = idx & (SS - 1);
        int bh = idx >> 13;
        int hh = bh & 7, b = bh >> 3;

        const float* qp = qk + ((size_t)b * SS + t) * DD;
        float q[64];
#pragma unroll
        for (int k = 0; k < 64; k++) q[k] = qp[k];

        const float* rbase = rot + hh * 64;
        float maxv = -1e30f, minv = 1e30f;
        int maxi = 0, mini = 0;
        for (int i = 0; i < 64; i++) {
            float s0 = 0.f, s1 = 0.f, s2 = 0.f, s3 = 0.f;
#pragma unroll
            for (int k = 0; k < 16; k++) {
                s0 = fmaf(q[4 * k + 0], rbase[(4 * k + 0) * (HH * 64) + i], s0);
                s1 = fmaf(q[4 * k + 1], rbase[(4 * k + 1) * (HH * 64) + i], s1);
                s2 = fmaf(q[4 * k + 2], rbase[(4 * k + 2) * (HH * 64) + i], s2);
                s3 = fmaf(q[4 * k + 3], rbase[(4 * k + 3) * (HH * 64) + i], s3);
            }
            float vdot = (s0 + s1) + (s2 + s3);
            if (vdot > maxv) { maxv = vdot; maxi = i; }
            if (vdot < minv) { minv = vdot; mini = i; }
        }
        g_bucket[idx] = (maxv >= -minv) ? maxi : 64 + mini;
    }
}

// ---------------- kernel 2: stable counting sort (256 segments x 32 tokens) --
// dynamic smem: cnt 256*130*2 | bkt_s 256*36 | sumA/sumB/base 3*128*4 = 77312 B
#define CSTR2 130
#define BSTR2 36
#define SORT_SMEM 77312
__global__ void __launch_bounds__(256)
sort_kernel()
{
    extern __shared__ char sms[];
    unsigned short* cnt   = (unsigned short*)sms;                 // 66560 B
    unsigned char*  bkt_s = (unsigned char*)(sms + 66560);        // 9216 B
    int* sumA = (int*)(sms + 66560 + 9216);                       // 128
    int* sumB = sumA + 128;
    int* base = sumB + 128;

    int bh = blockIdx.x;
    const int4* gb4 = (const int4*)(g_bucket + bh * SS);
    int* out = g_st + bh * SS;
    int s = threadIdx.x;      // 0..255, segment id (32 tokens each)

    // coalesced staging: 8192 ints as 2048 int4 (8 per thread)
#pragma unroll
    for (int it = 0; it < 8; it++) {
        int idx = s + it * 256;
        int4 v = gb4[idx];
        uchar4 u;
        u.x = (unsigned char)v.x; u.y = (unsigned char)v.y;
        u.z = (unsigned char)v.z; u.w = (unsigned char)v.w;
        int seg = idx >> 3, j = idx & 7;
        *(uchar4*)(bkt_s + seg * BSTR2 + j * 4) = u;
    }
    for (int k = 0; k < 128; k++) cnt[s * CSTR2 + k] = 0;
    __syncthreads();

    // histogram: 32 tokens per segment
    for (int k = 0; k < 32; k++) {
        int bkt = bkt_s[s * BSTR2 + k];
        cnt[s * CSTR2 + bkt]++;
    }
    __syncthreads();

    // prefix: thread (hb, bk) scans its half of the 256 segments for bucket bk
    int hb = s >> 7, bk = s & 127;
    {
        int run = 0;
        int gs0 = hb << 7;
        for (int seg = 0; seg < 128; seg++) {
            int gseg = gs0 + seg;
            int vv = cnt[gseg * CSTR2 + bk];
            cnt[gseg * CSTR2 + bk] = (unsigned short)run;
            run += vv;
        }
        if (hb == 0) sumA[bk] = run; else sumB[bk] = run;
    }
    __syncthreads();
    if (s == 0) {
        int r = 0;
        for (int k = 0; k < 128; k++) { base[k] = r; r += sumA[k] + sumB[k]; }
    }
    __syncthreads();

    // stable placement: segment s places its 32 tokens in order
    int hoff = hb;   // second half adds first-half bucket totals
    for (int k = 0; k < 32; k++) {
        int t = s * 32 + k;
        int bkt = bkt_s[s * BSTR2 + k];
        int pos = base[bkt] + (hoff ? sumA[bkt] : 0) + cnt[s * CSTR2 + bkt];
        cnt[s * CSTR2 + bkt]++;
        out[pos] = t;
    }
}

// ---------------- kernel 3: HMMA bucketed attention (fp16 gather, meta-packed)
#define SM_K    0                       // 192 x 128 B fp16, XOR swizzle
#define SM_V    24576                   // 192 x 128 B fp16, XOR swizzle
#define SM_META 49152                   // 192 x uint2 {invn bits, id}
#define ATTN_SMEM 50688

__global__ void __launch_bounds__(256, 3)
attn_kernel()
{
    extern __shared__ char smc[];
    uint32_t sbase = smem_u32(smc);
    uint2* meta_s = (uint2*)(smc + SM_META);

    int blk = blockIdx.x;
    int b   = blk >> 9;
    int t   = blk & 511;
    int ch0 = 2 * t, ch1 = 2 * t + 1;
    int pc0 = (ch0 + NCHUNK - 1) & (NCHUNK - 1);

    int tid = threadIdx.x;
    int w = tid >> 5, l = tid & 31;
    int bSS = b * SS;

    if (tid < 192) {
        int pos = (tid < 64)  ? (ch0 * 64 + tid)
                : (tid < 128) ? (ch1 * 64 + tid - 64)
                              : (pc0 * 64 + tid - 128);
        int id = g_st[b * (HH * SS) + pos];
        uint2 m;
        m.x = __float_as_uint(g_invn[bSS + id]);
        m.y = (uint32_t)id;
        meta_s[tid] = m;
    }
    __syncthreads();

    // ---- gather fp16 rows (128 B each) into swizzled smem --------------------
    const uint4* kh4 = (const uint4*)g_kh;   // 16B units: token*8 + f8
    const uint4* vh4 = (const uint4*)g_vh;
    for (int i = tid; i < 1536; i += 256) {
        int row = i >> 3, f8 = i & 7;
        size_t src = (size_t)(bSS + (int)meta_s[row].y) * 8 + f8;
        uint32_t swo = (uint32_t)(row * 128 + f8 * 16) ^ ((uint32_t)(row & 7) << 4);
        *(uint4*)(smc + SM_K + swo) = kh4[src];
        *(uint4*)(smc + SM_V + swo) = vh4[src];
    }
    __syncthreads();

    // ---- scores: warp handles 16 q rows x 128 keys ---------------------------
    int p  = w >> 2;
    int qb = p * 64 + (w & 3) * 16;
    int g  = l >> 2, i4 = l & 3;
    int m8 = l >> 3, rin = l & 7;

    float acc[16][4];
#pragma unroll
    for (int nt = 0; nt < 16; nt++)
#pragma unroll
        for (int k = 0; k < 4; k++) acc[nt][k] = 0.f;

#pragma unroll
    for (int kk = 0; kk < 4; kk++) {
        uint32_t af[4];
        {
            int arow = qb + ((m8 & 1) << 3) + rin;
            int adb  = (kk * 16 + ((m8 >> 1) << 3)) * 2;
            uint32_t aaddr = sbase + SM_K + (uint32_t)(arow * 128)
                           + ((uint32_t)adb ^ ((uint32_t)(arow & 7) << 4));
            ldm_x4(af, aaddr);
        }
#pragma unroll
        for (int jp = 0; jp < 8; jp++) {
            int keycol = 16 * jp + ((m8 >> 1) << 3) + rin;
            int krow   = kmap(p, keycol);
            int bdb    = (kk * 16 + ((m8 & 1) << 3)) * 2;
            uint32_t baddr = sbase + SM_K + (uint32_t)(krow * 128)
                           + ((uint32_t)bdb ^ ((uint32_t)(krow & 7) << 4));
            uint32_t bf[4];
            ldm_x4(bf, baddr);
            mma16816(acc[2 * jp],     af, bf[0], bf[1]);
            mma16816(acc[2 * jp + 1], af, bf[2], bf[3]);
        }
    }

    // ---- scale + self-mask + warp-local softmax ------------------------------
    int r0 = qb + g, r1 = r0 + 8;
    int id0 = (int)meta_s[r0].y, id1 = (int)meta_s[r1].y;

#pragma unroll
    for (int nt = 0; nt < 16; nt++) {
        int ca = 8 * nt + 2 * i4;
        int ka = kmap(p, ca);                 // even -> uint4-aligned meta pair
        uint4 mm = *(const uint4*)(smc + SM_META + ka * 8);
        float sa = __uint_as_float(mm.x) * 0.125f;
        float sb = __uint_as_float(mm.z) * 0.125f;
        int ia = (int)mm.y, ib = (int)mm.w;
        acc[nt][0] = (ia == id0) ? SELF_VAL : acc[nt][0] * sa;
        acc[nt][1] = (ib == id0) ? SELF_VAL : acc[nt][1] * sb;
        acc[nt][2] = (ia == id1) ? SELF_VAL : acc[nt][2] * sa;
        acc[nt][3] = (ib == id1) ? SELF_VAL : acc[nt][3] * sb;
    }

    float m0 = -1e30f, m1 = -1e30f;
#pragma unroll
    for (int nt = 0; nt < 16; nt++) {
        m0 = fmaxf(m0, fmaxf(acc[nt][0], acc[nt][1]));
        m1 = fmaxf(m1, fmaxf(acc[nt][2], acc[nt][3]));
    }
    m0 = fmaxf(m0, __shfl_xor_sync(0xffffffffu, m0, 1));
    m0 = fmaxf(m0, __shfl_xor_sync(0xffffffffu, m0, 2));
    m1 = fmaxf(m1, __shfl_xor_sync(0xffffffffu, m1, 1));
    m1 = fmaxf(m1, __shfl_xor_sync(0xffffffffu, m1, 2));

    // exp + sum; pack fp16 P back INTO acc storage
    float s0 = 0.f, s1 = 0.f;
#pragma unroll
    for (int nt = 0; nt < 16; nt++) {
        float e0 = __expf(acc[nt][0] - m0);
        float e1 = __expf(acc[nt][1] - m0);
        float e2 = __expf(acc[nt][2] - m1);
        float e3 = __expf(acc[nt][3] - m1);
        s0 += e0 + e1; s1 += e2 + e3;
        acc[nt][0] = __uint_as_float(h2pack(e0, e1));
        acc[nt][1] = __uint_as_float(h2pack(e2, e3));
    }
    s0 += __shfl_xor_sync(0xffffffffu, s0, 1);
    s0 += __shfl_xor_sync(0xffffffffu, s0, 2);
    s1 += __shfl_xor_sync(0xffffffffu, s1, 1);
    s1 += __shfl_xor_sync(0xffffffffu, s1, 2);
    float inv0 = 1.0f / s0, inv1 = 1.0f / s1;

    int ch = (r0 < 64) ? ch0 : ch1;
    int h  = ch >> 7;
    if (i4 == 0) {
        g_logits[b * (HH * SS) + h * SS + id0] = m0 + __logf(s0);
        g_logits[b * (HH * SS) + h * SS + id1] = m1 + __logf(s1);
    }

    // ---- PV: A = P fragments straight from registers --------------------------
    float oacc[8][4];
#pragma unroll
    for (int nt = 0; nt < 8; nt++)
#pragma unroll
        for (int k = 0; k < 4; k++) oacc[nt][k] = 0.f;

#pragma unroll
    for (int kk = 0; kk < 8; kk++) {
        uint32_t pa[4];
        pa[0] = __float_as_uint(acc[2 * kk][0]);
        pa[1] = __float_as_uint(acc[2 * kk][1]);
        pa[2] = __float_as_uint(acc[2 * kk + 1][0]);
        pa[3] = __float_as_uint(acc[2 * kk + 1][1]);
        int keycol = kk * 16 + ((m8 & 1) << 3) + rin;
        int krow   = kmap(p, keycol);
#pragma unroll
        for (int n2 = 0; n2 < 4; n2++) {
            int vdb = (n2 * 16 + ((m8 >> 1) << 3)) * 2;
            uint32_t vaddr = sbase + SM_V + (uint32_t)(krow * 128)
                           + ((uint32_t)vdb ^ ((uint32_t)(krow & 7) << 4));
            uint32_t vb[4];
            ldm_x4t(vb, vaddr);
            mma16816(oacc[2 * n2],     pa, vb[0], vb[1]);
            mma16816(oacc[2 * n2 + 1], pa, vb[2], vb[3]);
        }
    }

    // ---- write outputs (normalize here; fp16x2 packed) ------------------------
    uint32_t* o0 = g_oh + ((size_t)b * (HH * SS) + (size_t)h * SS + id0) * 32;
    uint32_t* o1 = g_oh + ((size_t)b * (HH * SS) + (size_t)h * SS + id1) * 32;
#pragma unroll
    for (int nt = 0; nt < 8; nt++) {
        int dp = 4 * nt + i4;
        o0[dp] = h2pack(oacc[nt][0] * inv0, oacc[nt][1] * inv0);
        o1[dp] = h2pack(oacc[nt][2] * inv1, oacc[nt][3] * inv1);
    }
}

// ---------------- kernel 4: combine hash rounds (vectorized, 8 floats/thread)
__global__ void combine_kernel(float* __restrict__ out)
{
    int gidx = blockIdx.x * 256 + threadIdx.x;   // [0, 524288)
    int dq = gidx & 7;        // dim quad: 4 half2 = 8 floats
    int g  = gidx >> 3;       // token index within B*S
    int b  = g >> 13;
    int s  = g & (SS - 1);

    float lg[HH];
    float m = -1e30f;
#pragma unroll
    for (int h = 0; h < HH; h++) {
        lg[h] = g_logits[b * (HH * SS) + h * SS + s];
        m = fmaxf(m, lg[h]);
    }
    float sum = 0.f;
#pragma unroll
    for (int h = 0; h < HH; h++) { lg[h] = __expf(lg[h] - m); sum += lg[h]; }
    float inv = 1.0f / sum;

    float a[8];
#pragma unroll
    for (int k = 0; k < 8; k++) a[k] = 0.f;

#pragma unroll
    for (int h = 0; h < HH; h++) {
        uint4 u = ((const uint4*)g_oh)[((size_t)b * (HH * SS) + h * SS + s) * 8 + dq];
        float wgt = lg[h] * inv;
        float2 f0 = __half22float2(*(__half2*)&u.x);
        float2 f1 = __half22float2(*(__half2*)&u.y);
        float2 f2 = __half22float2(*(__half2*)&u.z);
        float2 f3 = __half22float2(*(__half2*)&u.w);
        a[0] += wgt * f0.x; a[1] += wgt * f0.y;
        a[2] += wgt * f1.x; a[3] += wgt * f1.y;
        a[4] += wgt * f2.x; a[5] += wgt * f2.y;
        a[6] += wgt * f3.x; a[7] += wgt * f3.y;
    }
    float* op = out + ((size_t)b * SS + s) * DD + dq * 8;
    float4 r0; r0.x = a[0]; r0.y = a[1]; r0.z = a[2]; r0.w = a[3];
    float4 r1; r1.x = a[4]; r1.y = a[5]; r1.z = a[6]; r1.w = a[7];
    *(float4*)op = r0;
    *(float4*)(op + 4) = r1;
}

// ---------------- launcher -----------------------------------------------------
extern "C" void kernel_launch(void* const* d_in, const int* in_sizes, int n_in,
                              void* d_out, int out_size)
{
    const float* qk  = (const float*)d_in[0];
    const float* v   = (const float*)d_in[1];
    const float* rot = (const float*)d_in[2];
    float* out = (float*)d_out;
    (void)in_sizes; (void)n_in; (void)out_size;

    cudaFuncSetAttribute(attn_kernel,
                         cudaFuncAttributeMaxDynamicSharedMemorySize, ATTN_SMEM);
    cudaFuncSetAttribute(sort_kernel,
                         cudaFuncAttributeMaxDynamicSharedMemorySize, SORT_SMEM);

    rsplit_kernel<<<32, 256>>>(rot);
    prep_kernel<<<(BB * SS * 16) / 256, 256>>>(qk, v);
    hash_kernel<<<BB * HH * 64, 256>>>(qk, rot);
    hash_fix_kernel<<<64, 128>>>(qk, rot);
    sort_kernel<<<BB * HH, 256, SORT_SMEM>>>();
    attn_kernel<<<BB * 512, 256, ATTN_SMEM>>>();
    combine_kernel<<<(BB * SS * 8) / 256, 256>>>(out);
}

// round 17
// speedup vs baseline: 1.2115x; 1.2115x over previous
#include <cuda_runtime.h>
#include <cuda_fp16.h>
#include <math.h>
#include <stdint.h>

// Problem constants
#define BB 8
#define SS 8192
#define DD 64
#define HH 8
#define NCHUNK 1024
#define SELF_VAL -5e4f

// ---------------- warp MMA helpers (sm_80-class, compute_103-safe) -----------
__device__ __forceinline__ uint32_t smem_u32(const void* p) {
    uint32_t a;
    asm("{ .reg .u64 t; cvta.to.shared.u64 t, %1; cvt.u32.u64 %0, t; }"
        : "=r"(a) : "l"(p));
    return a;
}
__device__ __forceinline__ void ldm_x4(uint32_t* r, uint32_t addr) {
    asm volatile("ldmatrix.sync.aligned.m8n8.x4.shared.b16 {%0,%1,%2,%3}, [%4];"
                 : "=r"(r[0]), "=r"(r[1]), "=r"(r[2]), "=r"(r[3]) : "r"(addr));
}
__device__ __forceinline__ void ldm_x4t(uint32_t* r, uint32_t addr) {
    asm volatile("ldmatrix.sync.aligned.m8n8.x4.trans.shared.b16 {%0,%1,%2,%3}, [%4];"
                 : "=r"(r[0]), "=r"(r[1]), "=r"(r[2]), "=r"(r[3]) : "r"(addr));
}
__device__ __forceinline__ void mma16816(float* c, const uint32_t* a,
                                         uint32_t b0, uint32_t b1) {
    asm volatile(
        "mma.sync.aligned.m16n8k16.row.col.f32.f16.f16.f32 "
        "{%0,%1,%2,%3}, {%4,%5,%6,%7}, {%8,%9}, {%0,%1,%2,%3};"
        : "+f"(c[0]), "+f"(c[1]), "+f"(c[2]), "+f"(c[3])
        : "r"(a[0]), "r"(a[1]), "r"(a[2]), "r"(a[3]), "r"(b0), "r"(b1));
}
__device__ __forceinline__ uint32_t h2pack(float x, float y) {
    __half2 h = __floats2half2_rn(x, y);
    return *(uint32_t*)&h;
}
__device__ __forceinline__ uint32_t hpackh(__half x, __half y) {
    __half2 h = __halves2half2(x, y);
    return *(uint32_t*)&h;
}

// key-column (0..127) -> tile row (0..191)
__device__ __forceinline__ int kmap(int p, int col) {
    if (p == 0) return (col < 64) ? col : col + 64;
    return (col < 64) ? col + 64 : col - 64;
}

// ---------------- scratch ----------------------------------------------------
__device__ int      g_bucket[BB * HH * SS];
__device__ int      g_st[BB * HH * SS];
__device__ float    g_logits[BB * HH * SS];
__device__ uint32_t g_oh[(size_t)BB * HH * SS * 32];   // fp16x2 outputs, 64 MB
__device__ uint32_t g_kh[(size_t)BB * SS * 32];        // fp16 qk hi-split, 8 MB
__device__ uint32_t g_klo[(size_t)BB * SS * 32];       // fp16 qk lo-split, 8 MB
__device__ uint32_t g_vh[(size_t)BB * SS * 32];        // fp16 v,  8 MB
__device__ uint32_t g_rhi[HH * 64 * 32];               // fp16 rot hi, 64 KB
__device__ uint32_t g_rlo[HH * 64 * 32];               // fp16 rot lo, 64 KB
__device__ float    g_invn[BB * SS];                   // exact fp32 inv-norms
__device__ int      g_nflag;                           // near-tie counter
__device__ int      g_flag[BB * HH * SS];              // flagged token-rounds

// ---------------- kernel 0a: rotation pre-split (once, not per hash block) ---
__global__ void rsplit_kernel(const float* __restrict__ rot)
{
    int idx = blockIdx.x * 256 + threadIdx.x;   // 0..8191 float4s
    int f   = idx >> 7;
    int rem = idx & 127;
    int h   = rem >> 4, i4 = rem & 15;

    float4 x = ((const float4*)rot)[idx];
    __half a0 = __float2half_rn(x.x), a1 = __float2half_rn(x.y);
    __half a2 = __float2half_rn(x.z), a3 = __float2half_rn(x.w);
    uint2 hiv; hiv.x = hpackh(a0, a1); hiv.y = hpackh(a2, a3);
    uint2 lov;
    lov.x = h2pack(x.x - __half2float(a0), x.y - __half2float(a1));
    lov.y = h2pack(x.z - __half2float(a2), x.w - __half2float(a3));
    int dst = (h * 64 + f) * 16 + i4;
    ((uint2*)g_rhi)[dst] = hiv;
    ((uint2*)g_rlo)[dst] = lov;
}

// ---------------- kernel 0b: fp16 pre-pass (hi+lo split) + exact norms -------
__global__ void prep_kernel(const float* __restrict__ qk,
                            const float* __restrict__ v)
{
    if (blockIdx.x == 0 && threadIdx.x == 0) g_nflag = 0;

    int idx = blockIdx.x * 256 + threadIdx.x;   // token*16 + f4
    int f4  = idx & 15;
    int tok = idx >> 4;

    float4 kx = ((const float4*)qk)[idx];
    float4 vx = ((const float4*)v)[idx];

    __half a0 = __float2half_rn(kx.x), a1 = __float2half_rn(kx.y);
    __half a2 = __float2half_rn(kx.z), a3 = __float2half_rn(kx.w);
    uint2 kk; kk.x = hpackh(a0, a1); kk.y = hpackh(a2, a3);
    ((uint2*)g_kh)[tok * 16 + f4] = kk;
    uint2 kl;
    kl.x = h2pack(kx.x - __half2float(a0), kx.y - __half2float(a1));
    kl.y = h2pack(kx.z - __half2float(a2), kx.w - __half2float(a3));
    ((uint2*)g_klo)[tok * 16 + f4] = kl;

    uint2 vv; vv.x = h2pack(vx.x, vx.y); vv.y = h2pack(vx.z, vx.w);
    ((uint2*)g_vh)[tok * 16 + f4] = vv;

    float sq = kx.x * kx.x + kx.y * kx.y + kx.z * kx.z + kx.w * kx.w;
    sq += __shfl_xor_sync(0xffffffffu, sq, 1);
    sq += __shfl_xor_sync(0xffffffffu, sq, 2);
    sq += __shfl_xor_sync(0xffffffffu, sq, 4);
    sq += __shfl_xor_sync(0xffffffffu, sq, 8);
    if (f4 == 0) g_invn[tok] = 1.0f / (sqrtf(sq) + 1e-6f);
}

// ---------------- kernel 1: LSH hash stage A — fp16-split HMMA filter ---------
#define HQHI 0
#define HQLO 16384
#define HRHI 32768
#define HRLO 40960

#define TOP2(v, c, v1, i1, v2) do {                                   \
    float _av = fabsf(v);                                             \
    int _ci = ((v) >= 0.f) ? (c) : (64 + (c));                        \
    if (_av > (v1) || (_av == (v1) && _ci < (i1))) {                  \
        (v2) = (v1); (v1) = _av; (i1) = _ci;                          \
    } else (v2) = fmaxf((v2), _av); } while (0)

#define MERGE2(v1, i1, v2, m) do {                                    \
    float _ov1 = __shfl_xor_sync(0xffffffffu, (v1), (m));             \
    int   _oi1 = __shfl_xor_sync(0xffffffffu, (i1), (m));             \
    float _ov2 = __shfl_xor_sync(0xffffffffu, (v2), (m));             \
    if (_ov1 > (v1) || (_ov1 == (v1) && _oi1 < (i1))) {               \
        (v2) = fmaxf((v1), _ov2); (v1) = _ov1; (i1) = _oi1;           \
    } else (v2) = fmaxf((v2), _ov1); } while (0)

__global__ void __launch_bounds__(256)
hash_kernel(const float* __restrict__ qk, const float* __restrict__ rot)
{
    __shared__ char sm[49152];
    uint32_t sbase = smem_u32(sm);

    int blk  = blockIdx.x;
    int tile = blk & 63;
    int h    = (blk >> 6) & 7;
    int b    = blk >> 9;
    int tid  = threadIdx.x;
    int w = tid >> 5, l = tid & 31;

    // ---- Q load: pre-split fp16 hi/lo straight from global (coalesced) -------
    const uint4* kh4 = (const uint4*)g_kh + ((size_t)b * SS + tile * 128) * 8;
    const uint4* kl4 = (const uint4*)g_klo + ((size_t)b * SS + tile * 128) * 8;
#pragma unroll
    for (int it = 0; it < 4; it++) {
        int idx = tid + it * 256;        // 0..1023 = row*8 + f8
        int row = idx >> 3, f8 = idx & 7;
        uint32_t off = (uint32_t)(row * 128 + f8 * 16) ^ ((uint32_t)(row & 7) << 4);
        *(uint4*)(sm + HQHI + off) = kh4[idx];
        *(uint4*)(sm + HQLO + off) = kl4[idx];
    }

    // ---- R load: pre-split fp16 hi/lo straight from global (coalesced) -------
    const uint4* rh4 = (const uint4*)g_rhi + h * 512;   // 64 rows x 8 uint4
    const uint4* rl4 = (const uint4*)g_rlo + h * 512;
#pragma unroll
    for (int it = 0; it < 2; it++) {
        int idx = tid + it * 256;        // 0..511 = f*8 + f8
        int f = idx >> 3, f8 = idx & 7;
        uint32_t off = (uint32_t)(f * 128 + f8 * 16) ^ ((uint32_t)(f & 7) << 4);
        *(uint4*)(sm + HRHI + off) = rh4[idx];
        *(uint4*)(sm + HRLO + off) = rl4[idx];
    }
    __syncthreads();

    // ---- MMA: warp w handles rows w*16..+15, all 64 rotation cols -------------
    int qb = w * 16;
    int g  = l >> 2, i4 = l & 3;
    int m8 = l >> 3, rin = l & 7;

    float acc[8][4];
#pragma unroll
    for (int nt = 0; nt < 8; nt++)
#pragma unroll
        for (int k = 0; k < 4; k++) acc[nt][k] = 0.f;

#pragma unroll
    for (int kk = 0; kk < 4; kk++) {
        int arow = qb + ((m8 & 1) << 3) + rin;
        uint32_t adb = (uint32_t)((kk * 16 + ((m8 >> 1) << 3)) * 2);
        uint32_t aoff = (uint32_t)(arow * 128) + (adb ^ ((uint32_t)(arow & 7) << 4));
        uint32_t ahi[4], alo[4];
        ldm_x4(ahi, sbase + HQHI + aoff);
        ldm_x4(alo, sbase + HQLO + aoff);

        int brow = kk * 16 + ((m8 & 1) << 3) + rin;
#pragma unroll
        for (int n16 = 0; n16 < 4; n16++) {
            uint32_t bcol = (uint32_t)((n16 * 16 + ((m8 >> 1) << 3)) * 2);
            uint32_t boff = (uint32_t)(brow * 128) + (bcol ^ ((uint32_t)(brow & 7) << 4));
            uint32_t bhi[4], blo[4];
            ldm_x4t(bhi, sbase + HRHI + boff);
            ldm_x4t(blo, sbase + HRLO + boff);
            mma16816(acc[2 * n16],     ahi, bhi[0], bhi[1]);
            mma16816(acc[2 * n16 + 1], ahi, bhi[2], bhi[3]);
            mma16816(acc[2 * n16],     alo, bhi[0], bhi[1]);
            mma16816(acc[2 * n16 + 1], alo, bhi[2], bhi[3]);
            mma16816(acc[2 * n16],     ahi, blo[0], blo[1]);
            mma16816(acc[2 * n16 + 1], ahi, blo[2], blo[3]);
        }
    }

    // ---- top-2 over the 128 concat candidates, per row ------------------------
    float v1a = -1e30f, v2a = -1e30f, v1b = -1e30f, v2b = -1e30f;
    int i1a = 0, i1b = 0;
#pragma unroll
    for (int nt = 0; nt < 8; nt++) {
        int c = nt * 8 + 2 * i4;
        TOP2(acc[nt][0], c,     v1a, i1a, v2a);
        TOP2(acc[nt][1], c + 1, v1a, i1a, v2a);
        TOP2(acc[nt][2], c,     v1b, i1b, v2b);
        TOP2(acc[nt][3], c + 1, v1b, i1b, v2b);
    }
    MERGE2(v1a, i1a, v2a, 1); MERGE2(v1a, i1a, v2a, 2);
    MERGE2(v1b, i1b, v2b, 1); MERGE2(v1b, i1b, v2b, 2);

    if (i4 == 0) {
        int base = (b * HH + h) * SS + tile * 128;
#pragma unroll
        for (int rr = 0; rr < 2; rr++) {
            int row = qb + g + rr * 8;
            float v1 = rr ? v1b : v1a, v2 = rr ? v2b : v2a;
            int i1 = rr ? i1b : i1a;
            int t = tile * 128 + row;
            float nq = 1.0f / g_invn[b * SS + t];
            float theta = 5e-5f + 2e-5f * nq;
            if (v1 - v2 > theta) {
                g_bucket[base + row] = i1;
            } else {
                int s = atomicAdd(&g_nflag, 1);
                g_flag[s] = base + row;
            }
        }
    }
}

// ---------------- kernel 1b: exact fp32 fallback (one WARP per token) ---------
// Lane l handles rotations i = l and i = l+32. Each dot keeps the bit-identical
// 4-chain fmaf order and (s0+s1)+(s2+s3) reduction; the argmax/argmin merge
// uses strict > / < with lower-index-wins ties = serial first-index semantics.
__global__ void __launch_bounds__(256)
hash_fix_kernel(const float* __restrict__ qk, const float* __restrict__ rot)
{
    int n = g_nflag;
    int wglob  = blockIdx.x * 8 + (threadIdx.x >> 5);
    int wtotal = gridDim.x * 8;
    int l = threadIdx.x & 31;

    for (int e = wglob; e < n; e += wtotal) {
        int idx = g_flag[e];
        int t  = idx & (SS - 1);
        int bh = idx >> 13;
        int hh = bh & 7, b = bh >> 3;

        // q loads are warp-uniform (broadcast)
        const float* qp = qk + ((size_t)b * SS + t) * DD;
        float q[64];
#pragma unroll
        for (int k = 0; k < 64; k++) q[k] = __ldg(qp + k);

        const float* rbase = rot + hh * 64;
        float maxv = -1e30f, minv = 1e30f;
        int maxi = l, mini = l;
#pragma unroll
        for (int half = 0; half < 2; half++) {
            int i = l + half * 32;
            float s0 = 0.f, s1 = 0.f, s2 = 0.f, s3 = 0.f;
#pragma unroll
            for (int k = 0; k < 16; k++) {
                s0 = fmaf(q[4 * k + 0], rbase[(4 * k + 0) * (HH * 64) + i], s0);
                s1 = fmaf(q[4 * k + 1], rbase[(4 * k + 1) * (HH * 64) + i], s1);
                s2 = fmaf(q[4 * k + 2], rbase[(4 * k + 2) * (HH * 64) + i], s2);
                s3 = fmaf(q[4 * k + 3], rbase[(4 * k + 3) * (HH * 64) + i], s3);
            }
            float vdot = (s0 + s1) + (s2 + s3);
            if (vdot > maxv) { maxv = vdot; maxi = i; }   // strict > : first i wins
            if (vdot < minv) { minv = vdot; mini = i; }
        }
        // warp reduce, lower-index-wins on exact ties
#pragma unroll
        for (int m = 1; m < 32; m <<= 1) {
            float ov = __shfl_xor_sync(0xffffffffu, maxv, m);
            int   oi = __shfl_xor_sync(0xffffffffu, maxi, m);
            if (ov > maxv || (ov == maxv && oi < maxi)) { maxv = ov; maxi = oi; }
            ov = __shfl_xor_sync(0xffffffffu, minv, m);
            oi = __shfl_xor_sync(0xffffffffu, mini, m);
            if (ov < minv || (ov == minv && oi < mini)) { minv = ov; mini = oi; }
        }
        if (l == 0)
            g_bucket[idx] = (maxv >= -minv) ? maxi : 64 + mini;
    }
}

// ---------------- kernel 2: stable counting sort (256 segments x 32 tokens) --
#define CSTR2 130
#define BSTR2 36
#define SORT_SMEM 77312
__global__ void __launch_bounds__(256)
sort_kernel()
{
    extern __shared__ char sms[];
    unsigned short* cnt   = (unsigned short*)sms;                 // 66560 B
    unsigned char*  bkt_s = (unsigned char*)(sms + 66560);        // 9216 B
    int* sumA = (int*)(sms + 66560 + 9216);                       // 128
    int* sumB = sumA + 128;
    int* base = sumB + 128;

    int bh = blockIdx.x;
    const int4* gb4 = (const int4*)(g_bucket + bh * SS);
    int* out = g_st + bh * SS;
    int s = threadIdx.x;      // 0..255, segment id (32 tokens each)

#pragma unroll
    for (int it = 0; it < 8; it++) {
        int idx = s + it * 256;
        int4 v = gb4[idx];
        uchar4 u;
        u.x = (unsigned char)v.x; u.y = (unsigned char)v.y;
        u.z = (unsigned char)v.z; u.w = (unsigned char)v.w;
        int seg = idx >> 3, j = idx & 7;
        *(uchar4*)(bkt_s + seg * BSTR2 + j * 4) = u;
    }
    for (int k = 0; k < 128; k++) cnt[s * CSTR2 + k] = 0;
    __syncthreads();

    for (int k = 0; k < 32; k++) {
        int bkt = bkt_s[s * BSTR2 + k];
        cnt[s * CSTR2 + bkt]++;
    }
    __syncthreads();

    int hb = s >> 7, bk = s & 127;
    {
        int run = 0;
        int gs0 = hb << 7;
        for (int seg = 0; seg < 128; seg++) {
            int gseg = gs0 + seg;
            int vv = cnt[gseg * CSTR2 + bk];
            cnt[gseg * CSTR2 + bk] = (unsigned short)run;
            run += vv;
        }
        if (hb == 0) sumA[bk] = run; else sumB[bk] = run;
    }
    __syncthreads();
    if (s == 0) {
        int r = 0;
        for (int k = 0; k < 128; k++) { base[k] = r; r += sumA[k] + sumB[k]; }
    }
    __syncthreads();

    int hoff = hb;
    for (int k = 0; k < 32; k++) {
        int t = s * 32 + k;
        int bkt = bkt_s[s * BSTR2 + k];
        int pos = base[bkt] + (hoff ? sumA[bkt] : 0) + cnt[s * CSTR2 + bkt];
        cnt[s * CSTR2 + bkt]++;
        out[pos] = t;
    }
}

// ---------------- kernel 3: HMMA bucketed attention (fp16 gather, meta-packed)
#define SM_K    0                       // 192 x 128 B fp16, XOR swizzle
#define SM_V    24576                   // 192 x 128 B fp16, XOR swizzle
#define SM_META 49152                   // 192 x uint2 {invn bits, id}
#define ATTN_SMEM 50688

__global__ void __launch_bounds__(256, 3)
attn_kernel()
{
    extern __shared__ char smc[];
    uint32_t sbase = smem_u32(smc);
    uint2* meta_s = (uint2*)(smc + SM_META);

    int blk = blockIdx.x;
    int b   = blk >> 9;
    int t   = blk & 511;
    int ch0 = 2 * t, ch1 = 2 * t + 1;
    int pc0 = (ch0 + NCHUNK - 1) & (NCHUNK - 1);

    int tid = threadIdx.x;
    int w = tid >> 5, l = tid & 31;
    int bSS = b * SS;

    if (tid < 192) {
        int pos = (tid < 64)  ? (ch0 * 64 + tid)
                : (tid < 128) ? (ch1 * 64 + tid - 64)
                              : (pc0 * 64 + tid - 128);
        int id = g_st[b * (HH * SS) + pos];
        uint2 m;
        m.x = __float_as_uint(g_invn[bSS + id]);
        m.y = (uint32_t)id;
        meta_s[tid] = m;
    }
    __syncthreads();

    // ---- gather fp16 rows (128 B each) into swizzled smem --------------------
    const uint4* kh4 = (const uint4*)g_kh;   // 16B units: token*8 + f8
    const uint4* vh4 = (const uint4*)g_vh;
    for (int i = tid; i < 1536; i += 256) {
        int row = i >> 3, f8 = i & 7;
        size_t src = (size_t)(bSS + (int)meta_s[row].y) * 8 + f8;
        uint32_t swo = (uint32_t)(row * 128 + f8 * 16) ^ ((uint32_t)(row & 7) << 4);
        *(uint4*)(smc + SM_K + swo) = kh4[src];
        *(uint4*)(smc + SM_V + swo) = vh4[src];
    }
    __syncthreads();

    // ---- scores: warp handles 16 q rows x 128 keys ---------------------------
    int p  = w >> 2;
    int qb = p * 64 + (w & 3) * 16;
    int g  = l >> 2, i4 = l & 3;
    int m8 = l >> 3, rin = l & 7;

    float acc[16][4];
#pragma unroll
    for (int nt = 0; nt < 16; nt++)
#pragma unroll
        for (int k = 0; k < 4; k++) acc[nt][k] = 0.f;

#pragma unroll
    for (int kk = 0; kk < 4; kk++) {
        uint32_t af[4];
        {
            int arow = qb + ((m8 & 1) << 3) + rin;
            int adb  = (kk * 16 + ((m8 >> 1) << 3)) * 2;
            uint32_t aaddr = sbase + SM_K + (uint32_t)(arow * 128)
                           + ((uint32_t)adb ^ ((uint32_t)(arow & 7) << 4));
            ldm_x4(af, aaddr);
        }
#pragma unroll
        for (int jp = 0; jp < 8; jp++) {
            int keycol = 16 * jp + ((m8 >> 1) << 3) + rin;
            int krow   = kmap(p, keycol);
            int bdb    = (kk * 16 + ((m8 & 1) << 3)) * 2;
            uint32_t baddr = sbase + SM_K + (uint32_t)(krow * 128)
                           + ((uint32_t)bdb ^ ((uint32_t)(krow & 7) << 4));
            uint32_t bf[4];
            ldm_x4(bf, baddr);
            mma16816(acc[2 * jp],     af, bf[0], bf[1]);
            mma16816(acc[2 * jp + 1], af, bf[2], bf[3]);
        }
    }

    // ---- scale + self-mask + warp-local softmax ------------------------------
    int r0 = qb + g, r1 = r0 + 8;
    int id0 = (int)meta_s[r0].y, id1 = (int)meta_s[r1].y;

#pragma unroll
    for (int nt = 0; nt < 16; nt++) {
        int ca = 8 * nt + 2 * i4;
        int ka = kmap(p, ca);                 // even -> uint4-aligned meta pair
        uint4 mm = *(const uint4*)(smc + SM_META + ka * 8);
        float sa = __uint_as_float(mm.x) * 0.125f;
        float sb = __uint_as_float(mm.z) * 0.125f;
        int ia = (int)mm.y, ib = (int)mm.w;
        acc[nt][0] = (ia == id0) ? SELF_VAL : acc[nt][0] * sa;
        acc[nt][1] = (ib == id0) ? SELF_VAL : acc[nt][1] * sb;
        acc[nt][2] = (ia == id1) ? SELF_VAL : acc[nt][2] * sa;
        acc[nt][3] = (ib == id1) ? SELF_VAL : acc[nt][3] * sb;
    }

    float m0 = -1e30f, m1 = -1e30f;
#pragma unroll
    for (int nt = 0; nt < 16; nt++) {
        m0 = fmaxf(m0, fmaxf(acc[nt][0], acc[nt][1]));
        m1 = fmaxf(m1, fmaxf(acc[nt][2], acc[nt][3]));
    }
    m0 = fmaxf(m0, __shfl_xor_sync(0xffffffffu, m0, 1));
    m0 = fmaxf(m0, __shfl_xor_sync(0xffffffffu, m0, 2));
    m1 = fmaxf(m1, __shfl_xor_sync(0xffffffffu, m1, 1));
    m1 = fmaxf(m1, __shfl_xor_sync(0xffffffffu, m1, 2));

    // exp + sum; pack fp16 P back INTO acc storage
    float s0 = 0.f, s1 = 0.f;
#pragma unroll
    for (int nt = 0; nt < 16; nt++) {
        float e0 = __expf(acc[nt][0] - m0);
        float e1 = __expf(acc[nt][1] - m0);
        float e2 = __expf(acc[nt][2] - m1);
        float e3 = __expf(acc[nt][3] - m1);
        s0 += e0 + e1; s1 += e2 + e3;
        acc[nt][0] = __uint_as_float(h2pack(e0, e1));
        acc[nt][1] = __uint_as_float(h2pack(e2, e3));
    }
    s0 += __shfl_xor_sync(0xffffffffu, s0, 1);
    s0 += __shfl_xor_sync(0xffffffffu, s0, 2);
    s1 += __shfl_xor_sync(0xffffffffu, s1, 1);
    s1 += __shfl_xor_sync(0xffffffffu, s1, 2);
    float inv0 = 1.0f / s0, inv1 = 1.0f / s1;

    int ch = (r0 < 64) ? ch0 : ch1;
    int h  = ch >> 7;
    if (i4 == 0) {
        g_logits[b * (HH * SS) + h * SS + id0] = m0 + __logf(s0);
        g_logits[b * (HH * SS) + h * SS + id1] = m1 + __logf(s1);
    }

    // ---- PV: A = P fragments straight from registers --------------------------
    float oacc[8][4];
#pragma unroll
    for (int nt = 0; nt < 8; nt++)
#pragma unroll
        for (int k = 0; k < 4; k++) oacc[nt][k] = 0.f;

#pragma unroll
    for (int kk = 0; kk < 8; kk++) {
        uint32_t pa[4];
        pa[0] = __float_as_uint(acc[2 * kk][0]);
        pa[1] = __float_as_uint(acc[2 * kk][1]);
        pa[2] = __float_as_uint(acc[2 * kk + 1][0]);
        pa[3] = __float_as_uint(acc[2 * kk + 1][1]);
        int keycol = kk * 16 + ((m8 & 1) << 3) + rin;
        int krow   = kmap(p, keycol);
#pragma unroll
        for (int n2 = 0; n2 < 4; n2++) {
            int vdb = (n2 * 16 + ((m8 >> 1) << 3)) * 2;
            uint32_t vaddr = sbase + SM_V + (uint32_t)(krow * 128)
                           + ((uint32_t)vdb ^ ((uint32_t)(krow & 7) << 4));
            uint32_t vb[4];
            ldm_x4t(vb, vaddr);
            mma16816(oacc[2 * n2],     pa, vb[0], vb[1]);
            mma16816(oacc[2 * n2 + 1], pa, vb[2], vb[3]);
        }
    }

    // ---- write outputs (normalize here; fp16x2 packed) ------------------------
    uint32_t* o0 = g_oh + ((size_t)b * (HH * SS) + (size_t)h * SS + id0) * 32;
    uint32_t* o1 = g_oh + ((size_t)b * (HH * SS) + (size_t)h * SS + id1) * 32;
#pragma unroll
    for (int nt = 0; nt < 8; nt++) {
        int dp = 4 * nt + i4;
        o0[dp] = h2pack(oacc[nt][0] * inv0, oacc[nt][1] * inv0);
        o1[dp] = h2pack(oacc[nt][2] * inv1, oacc[nt][3] * inv1);
    }
}

// ---------------- kernel 4: combine hash rounds (vectorized, 8 floats/thread)
__global__ void combine_kernel(float* __restrict__ out)
{
    int gidx = blockIdx.x * 256 + threadIdx.x;   // [0, 524288)
    int dq = gidx & 7;        // dim quad: 4 half2 = 8 floats
    int g  = gidx >> 3;       // token index within B*S
    int b  = g >> 13;
    int s  = g & (SS - 1);

    float lg[HH];
    float m = -1e30f;
#pragma unroll
    for (int h = 0; h < HH; h++) {
        lg[h] = g_logits[b * (HH * SS) + h * SS + s];
        m = fmaxf(m, lg[h]);
    }
    float sum = 0.f;
#pragma unroll
    for (int h = 0; h < HH; h++) { lg[h] = __expf(lg[h] - m); sum += lg[h]; }
    float inv = 1.0f / sum;

    float a[8];
#pragma unroll
    for (int k = 0; k < 8; k++) a[k] = 0.f;

#pragma unroll
    for (int h = 0; h < HH; h++) {
        uint4 u = ((const uint4*)g_oh)[((size_t)b * (HH * SS) + h * SS + s) * 8 + dq];
        float wgt = lg[h] * inv;
        float2 f0 = __half22float2(*(__half2*)&u.x);
        float2 f1 = __half22float2(*(__half2*)&u.y);
        float2 f2 = __half22float2(*(__half2*)&u.z);
        float2 f3 = __half22float2(*(__half2*)&u.w);
        a[0] += wgt * f0.x; a[1] += wgt * f0.y;
        a[2] += wgt * f1.x; a[3] += wgt * f1.y;
        a[4] += wgt * f2.x; a[5] += wgt * f2.y;
        a[6] += wgt * f3.x; a[7] += wgt * f3.y;
    }
    float* op = out + ((size_t)b * SS + s) * DD + dq * 8;
    float4 r0; r0.x = a[0]; r0.y = a[1]; r0.z = a[2]; r0.w = a[3];
    float4 r1; r1.x = a[4]; r1.y = a[5]; r1.z = a[6]; r1.w = a[7];
    *(float4*)op = r0;
    *(float4*)(op + 4) = r1;
}

// ---------------- launcher -----------------------------------------------------
extern "C" void kernel_launch(void* const* d_in, const int* in_sizes, int n_in,
                              void* d_out, int out_size)
{
    const float* qk  = (const float*)d_in[0];
    const float* v   = (const float*)d_in[1];
    const float* rot = (const float*)d_in[2];
    float* out = (float*)d_out;
    (void)in_sizes; (void)n_in; (void)out_size;

    cudaFuncSetAttribute(attn_kernel,
                         cudaFuncAttributeMaxDynamicSharedMemorySize, ATTN_SMEM);
    cudaFuncSetAttribute(sort_kernel,
                         cudaFuncAttributeMaxDynamicSharedMemorySize, SORT_SMEM);

    rsplit_kernel<<<32, 256>>>(rot);
    prep_kernel<<<(BB * SS * 16) / 256, 256>>>(qk, v);
    hash_kernel<<<BB * HH * 64, 256>>>(qk, rot);
    hash_fix_kernel<<<128, 256>>>(qk, rot);
    sort_kernel<<<BB * HH, 256, SORT_SMEM>>>();
    attn_kernel<<<BB * 512, 256, ATTN_SMEM>>>();
    combine_kernel<<<(BB * SS * 8) / 256, 256>>>(out);
}